// round 14
// baseline (speedup 1.0000x reference)
#include <cuda_runtime.h>
#include <math.h>

// Problem constants
#define Bsz 512
#define Tn  256
#define Dn  81
#define Hn  128
#define Gn  512            // 4*H
#define RPB 4              // batch rows per block
#define NTH 1024           // threads per block (32 warps)
#define NBLK (Bsz / RPB)   // 128 blocks
#define DPAD 84            // D padded to multiple of 4
#define A1PAD 132          // a1 row stride (conflict-free 4-lane stores)
#define GPAD 516           // gates row stride (conflict-free 4-lane stores)

// Shared memory layout (float offsets; all multiples of 4 -> 16B aligned)
#define OFF_WIH   0                          // [512][84] (cols 81..83 zero)
#define OFF_BIAS  (OFF_WIH + Gn*DPAD)        // [512] b_ih + b_hh
#define OFF_B1    (OFF_BIAS + Gn)            // [128]
#define OFF_B2    (OFF_B1 + Hn)              // [84]
#define OFF_H     (OFF_B2 + DPAD)            // [4][128]
#define OFF_C     (OFF_H + RPB*Hn)           // [4][128]
#define OFF_A1    (OFF_C + RPB*Hn)           // [4][132]
#define OFF_G     (OFF_A1 + RPB*A1PAD)       // [4][516]
#define OFF_XW    (OFF_G + RPB*GPAD)         // [4][84] (cols 81..83 zero)
#define OFF_E     (OFF_XW + RPB*DPAD)        // [4][84]
#define SMEM_FLOATS (OFF_E + RPB*DPAD)

// Fast transcendentals (MUFU-based). Overflow-safe forms.
__device__ __forceinline__ float sigmoid_f(float x) {
    return __fdividef(1.0f, 1.0f + __expf(-x));
}
__device__ __forceinline__ float tanh_f(float x) {
    float ax = fabsf(x);
    float e  = __expf(-2.0f * ax);          // in (0, 1], no overflow
    float r  = __fdividef(1.0f - e, 1.0f + e);
    return copysignf(r, x);
}

__device__ __forceinline__ float dot4(float4 w, float4 v, float acc) {
    return fmaf(w.x, v.x, fmaf(w.y, v.y, fmaf(w.z, v.z, fmaf(w.w, v.w, acc))));
}

// Streaming store (evict-first): outputs are write-once, never re-read.
__device__ __forceinline__ void stcs(float* p, float v) {
    __stcs(p, v);
}

// Reduce 4 per-lane partials (p[r] = partial for batch row r) over ALL 32
// lanes. 6 shfls. Lanes 0..3 end with full sums for rows o = {0,2,1,3}.
__device__ __forceinline__ void reduce4_32(const float p[4], int lane,
                                           float& d, int& o) {
    const bool b0 = (lane & 1);
    float q0 = b0 ? p[0] : p[2];
    float q1 = b0 ? p[1] : p[3];
    float v0 = __shfl_xor_sync(0xffffffffu, q0, 1);
    float v1 = __shfl_xor_sync(0xffffffffu, q1, 1);
    float a0 = (b0 ? p[2] : p[0]) + v0;
    float a1 = (b0 ? p[3] : p[1]) + v1;
    const bool b1 = (lane & 2);
    float q = b1 ? a0 : a1;
    float v = __shfl_xor_sync(0xffffffffu, q, 2);
    d = (b1 ? a1 : a0) + v;
    d += __shfl_xor_sync(0xffffffffu, d, 4);
    d += __shfl_xor_sync(0xffffffffu, d, 8);
    d += __shfl_xor_sync(0xffffffffu, d, 16);
    o = (b0 ? 2 : 0) | (b1 ? 1 : 0);
}

__global__ __launch_bounds__(NTH, 1)
void encoder_kernel(const float* __restrict__ X,
                    const float* __restrict__ W1,
                    const float* __restrict__ b1,
                    const float* __restrict__ W2,
                    const float* __restrict__ b2,
                    const float* __restrict__ Wih,
                    const float* __restrict__ Whh,
                    const float* __restrict__ bih,
                    const float* __restrict__ bhh,
                    float* __restrict__ outH,
                    float* __restrict__ outA)
{
    extern __shared__ float sm[];
    float* sWih  = sm + OFF_WIH;
    float* sbias = sm + OFF_BIAS;
    float* sb1   = sm + OFF_B1;
    float* sb2   = sm + OFF_B2;
    float* sh    = sm + OFF_H;
    float* sc    = sm + OFF_C;
    float* sa1   = sm + OFF_A1;
    float* sgate = sm + OFF_G;
    float* sxw   = sm + OFF_XW;
    float* se    = sm + OFF_E;

    const int tid  = threadIdx.x;
    const int wid  = tid >> 5;          // 0..31
    const int lane = tid & 31;          // K-chunk owner: floats 4*lane..4*lane+3
    const int b0i  = blockIdx.x * RPB;

    // ---- One-time loads into SMEM ----
    for (int i = tid; i < Gn * DPAD; i += NTH) {
        int row = i / DPAD, col = i - row * DPAD;
        sWih[i] = (col < Dn) ? Wih[row * Dn + col] : 0.0f;
    }
    for (int i = tid; i < Gn; i += NTH) sbias[i] = bih[i] + bhh[i];
    if (tid < Hn)   sb1[tid] = b1[tid];
    if (tid < DPAD) sb2[tid] = (tid < Dn) ? b2[tid] : 0.0f;
    for (int i = tid; i < RPB * Hn; i += NTH) { sh[i] = 0.0f; sc[i] = 0.0f; }
    __syncthreads();

    for (int t = 0; t < Tn; ++t) {
        // ---- Prefetch x_t for Phase C (warps 0..3); hidden under A/B ----
        float xv0 = 0.f, xv1 = 0.f, xv2 = 0.f;
        if (wid < 4) {
            const float* xrow = X + ((size_t)(b0i + wid) * Tn + t) * Dn;
            xv0 = xrow[lane];
            xv1 = xrow[lane + 32];
            if (lane < Dn - 64) xv2 = xrow[lane + 64];
        }

        // ---- h,c K-slices into registers (reused by Phases A and D) ----
        float4 hA[4], cA[4];
        #pragma unroll
        for (int r = 0; r < RPB; ++r) {
            hA[r] = *(const float4*)(sh + r * Hn + 4 * lane);
            cA[r] = *(const float4*)(sc + r * Hn + 4 * lane);
        }

        // ===== Phase A: a1 = tanh(W1 @ [h;c] + b1); 4 j per warp =====
        {
            #pragma unroll
            for (int oi = 0; oi < 4; ++oi) {
                const int j = wid * 4 + oi;
                const float4* w = (const float4*)(W1 + (size_t)j * (2 * Hn));
                float4 wh = __ldcs(w + lane);        // streaming: never L1-resident
                float4 wc = __ldcs(w + 32 + lane);
                float p[4];
                #pragma unroll
                for (int r = 0; r < RPB; ++r)
                    p[r] = dot4(wc, cA[r], dot4(wh, hA[r], 0.0f));
                float d; int o;
                reduce4_32(p, lane, d, o);
                if (lane < 4) sa1[o * A1PAD + j] = tanh_f(d + sb1[j]);
            }
        }
        __syncthreads();

        // ===== Phase B: e = W2 @ a1 + b2; 3 j per warp (warps 0..26) =====
        if (wid < 27) {
            float4 aA[4];
            #pragma unroll
            for (int r = 0; r < RPB; ++r)
                aA[r] = *(const float4*)(sa1 + r * A1PAD + 4 * lane);
            #pragma unroll
            for (int oi = 0; oi < 3; ++oi) {
                const int j = wid * 3 + oi;
                float4 w = __ldg((const float4*)(W2 + (size_t)j * Hn) + lane); // L1-resident
                float p[4];
                #pragma unroll
                for (int r = 0; r < RPB; ++r)
                    p[r] = dot4(w, aA[r], 0.0f);
                float d; int o;
                reduce4_32(p, lane, d, o);
                if (lane < 4) se[o * DPAD + j] = d + sb2[j];
            }
        }
        __syncthreads();

        // ===== Phase C: softmax over D (NO max-sub: |e| <= ~11 provably,
        // exp(e) <= 9e4, fp32-safe); alpha out; xw = alpha*x (warps 0..3) =====
        if (wid < 4) {
            const int cr = wid;
            const int cl = lane;
            float* er = se + cr * DPAD;
            float e0 = __expf(er[cl]);
            float e1 = __expf(er[cl + 32]);
            float e2 = (cl < Dn - 64) ? __expf(er[cl + 64]) : 0.0f;
            float ssum = e0 + e1 + e2;
            #pragma unroll
            for (int s = 16; s; s >>= 1) ssum += __shfl_xor_sync(0xffffffffu, ssum, s);
            const float inv = __fdividef(1.0f, ssum);

            float* xwr  = sxw + cr * DPAD;
            float* arow = outA + ((size_t)(b0i + cr) * Tn + t) * Dn;

            float a0 = e0 * inv;
            stcs(arow + cl, a0);          xwr[cl]      = a0 * xv0;
            float a1v = e1 * inv;
            stcs(arow + cl + 32, a1v);    xwr[cl + 32] = a1v * xv1;
            if (cl < Dn - 64) {
                float a2 = e2 * inv;
                stcs(arow + cl + 64, a2); xwr[cl + 64] = a2 * xv2;
            }
            if (cl < DPAD - Dn) xwr[Dn + cl] = 0.0f;   // zero pad cols 81..83
        }
        __syncthreads();

        // ===== Phase D: gates = W_ih @ xw + W_hh @ h + bias; 16 j/warp =====
        {
            const bool act21 = (lane < 21);      // 4*lane < 84
            float4 zz = make_float4(0.f, 0.f, 0.f, 0.f);
            float4 xwA[4];
            #pragma unroll
            for (int r = 0; r < RPB; ++r)
                xwA[r] = act21 ? *(const float4*)(sxw + r * DPAD + 4 * lane) : zz;

            #pragma unroll 4
            for (int oi = 0; oi < 16; ++oi) {
                const int j = wid * 16 + oi;
                float4 wh4 = __ldcs((const float4*)(Whh + (size_t)j * Hn) + lane);
                // predicated: inactive lanes contribute zero, fetch nothing
                float4 wi4 = act21 ? ((const float4*)(sWih + j * DPAD))[lane] : zz;
                float p[4];
                #pragma unroll
                for (int r = 0; r < RPB; ++r)
                    p[r] = dot4(wh4, hA[r], dot4(wi4, xwA[r], 0.0f));
                float d; int o;
                reduce4_32(p, lane, d, o);
                if (lane < 4) sgate[o * GPAD + j] = d + sbias[j];
            }
        }
        __syncthreads();

        // ===== Phase E: LSTM cell update, write h out (512 threads) =====
        if (tid < RPB * Hn) {
            const int rr  = tid >> 7;
            const int col = tid & (Hn - 1);
            float gi = sgate[rr * GPAD + col];
            float gf = sgate[rr * GPAD + Hn + col];
            float gg = sgate[rr * GPAD + 2 * Hn + col];
            float go = sgate[rr * GPAD + 3 * Hn + col];
            float si = sigmoid_f(gi);
            float sf = sigmoid_f(gf);
            float so = sigmoid_f(go);
            float cn = sf * sc[rr * Hn + col] + si * tanh_f(gg);
            float hn = so * tanh_f(cn);
            sc[rr * Hn + col] = cn;
            sh[rr * Hn + col] = hn;
            stcs(outH + ((size_t)(b0i + rr) * Tn + t) * Hn + col, hn);
        }
        __syncthreads();
    }
}

extern "C" void kernel_launch(void* const* d_in, const int* in_sizes, int n_in,
                              void* d_out, int out_size)
{
    const float* X    = (const float*)d_in[0];
    const float* W1   = (const float*)d_in[1];
    const float* b1   = (const float*)d_in[2];
    const float* W2   = (const float*)d_in[3];
    const float* b2   = (const float*)d_in[4];
    const float* Wih  = (const float*)d_in[5];
    const float* Whh  = (const float*)d_in[6];
    const float* bih  = (const float*)d_in[7];
    const float* bhh  = (const float*)d_in[8];

    float* outH = (float*)d_out;                          // [B, T, H]
    float* outA = outH + (size_t)Bsz * Tn * Hn;           // [B, T, D]

    const size_t smem_bytes = (size_t)SMEM_FLOATS * sizeof(float);
    cudaFuncSetAttribute(encoder_kernel,
                         cudaFuncAttributeMaxDynamicSharedMemorySize,
                         (int)smem_bytes);

    encoder_kernel<<<NBLK, NTH, smem_bytes>>>(
        X, W1, b1, W2, b2, Wih, Whh, bih, bhh, outH, outA);
}

// round 15
// speedup vs baseline: 1.0534x; 1.0534x over previous
#include <cuda_runtime.h>
#include <math.h>

// Problem constants
#define Bsz 512
#define Tn  256
#define Dn  81
#define Hn  128
#define Gn  512            // 4*H
#define RPB 4              // batch rows per block
#define NTH 1024           // threads per block (32 warps)
#define NBLK (Bsz / RPB)   // 128 blocks
#define DPAD 84            // D padded to multiple of 4
#define A1PAD 132          // a1 row stride (conflict-free 4-lane stores)
#define GPAD 516           // gates row stride (conflict-free 4-lane stores)

// Shared memory layout (float offsets; all multiples of 4 -> 16B aligned)
#define OFF_WIH   0                          // [512][84] (cols 81..83 zero)
#define OFF_BIAS  (OFF_WIH + Gn*DPAD)        // [512] b_ih + b_hh
#define OFF_B1    (OFF_BIAS + Gn)            // [128]
#define OFF_B2    (OFF_B1 + Hn)              // [84]
#define OFF_H     (OFF_B2 + DPAD)            // [4][128]
#define OFF_C     (OFF_H + RPB*Hn)           // [4][128]
#define OFF_A1    (OFF_C + RPB*Hn)           // [4][132]
#define OFF_G     (OFF_A1 + RPB*A1PAD)       // [4][516]
#define OFF_XW    (OFF_G + RPB*GPAD)         // [4][84] (cols 81..83 zero)
#define OFF_E     (OFF_XW + RPB*DPAD)        // [4][84]
#define SMEM_FLOATS (OFF_E + RPB*DPAD)

// Fast transcendentals (MUFU-based). Overflow-safe forms.
__device__ __forceinline__ float sigmoid_f(float x) {
    return __fdividef(1.0f, 1.0f + __expf(-x));
}
__device__ __forceinline__ float tanh_f(float x) {
    float ax = fabsf(x);
    float e  = __expf(-2.0f * ax);          // in (0, 1], no overflow
    float r  = __fdividef(1.0f - e, 1.0f + e);
    return copysignf(r, x);
}

__device__ __forceinline__ float dot4(float4 w, float4 v, float acc) {
    return fmaf(w.x, v.x, fmaf(w.y, v.y, fmaf(w.z, v.z, fmaf(w.w, v.w, acc))));
}

// Streaming store (evict-first): outputs are write-once, never re-read.
__device__ __forceinline__ void stcs(float* p, float v) {
    __stcs(p, v);
}

// Reduce 4 per-lane partials (p[r] = partial for batch row r) over ALL 32
// lanes. 6 shfls. Lanes 0..3 end with full sums for rows o = {0,2,1,3}.
__device__ __forceinline__ void reduce4_32(const float p[4], int lane,
                                           float& d, int& o) {
    const bool b0 = (lane & 1);
    float q0 = b0 ? p[0] : p[2];
    float q1 = b0 ? p[1] : p[3];
    float v0 = __shfl_xor_sync(0xffffffffu, q0, 1);
    float v1 = __shfl_xor_sync(0xffffffffu, q1, 1);
    float a0 = (b0 ? p[2] : p[0]) + v0;
    float a1 = (b0 ? p[3] : p[1]) + v1;
    const bool b1 = (lane & 2);
    float q = b1 ? a0 : a1;
    float v = __shfl_xor_sync(0xffffffffu, q, 2);
    d = (b1 ? a1 : a0) + v;
    d += __shfl_xor_sync(0xffffffffu, d, 4);
    d += __shfl_xor_sync(0xffffffffu, d, 8);
    d += __shfl_xor_sync(0xffffffffu, d, 16);
    o = (b0 ? 2 : 0) | (b1 ? 1 : 0);
}

__global__ __launch_bounds__(NTH, 1)
void encoder_kernel(const float* __restrict__ X,
                    const float* __restrict__ W1,
                    const float* __restrict__ b1,
                    const float* __restrict__ W2,
                    const float* __restrict__ b2,
                    const float* __restrict__ Wih,
                    const float* __restrict__ Whh,
                    const float* __restrict__ bih,
                    const float* __restrict__ bhh,
                    float* __restrict__ outH,
                    float* __restrict__ outA)
{
    extern __shared__ float sm[];
    float* sWih  = sm + OFF_WIH;
    float* sbias = sm + OFF_BIAS;
    float* sb1   = sm + OFF_B1;
    float* sb2   = sm + OFF_B2;
    float* sh    = sm + OFF_H;
    float* sc    = sm + OFF_C;
    float* sa1   = sm + OFF_A1;
    float* sgate = sm + OFF_G;
    float* sxw   = sm + OFF_XW;
    float* se    = sm + OFF_E;

    const int tid  = threadIdx.x;
    const int wid  = tid >> 5;          // 0..31
    const int lane = tid & 31;          // K-chunk owner: floats 4*lane..4*lane+3
    const int b0i  = blockIdx.x * RPB;

    // ---- One-time loads into SMEM ----
    for (int i = tid; i < Gn * DPAD; i += NTH) {
        int row = i / DPAD, col = i - row * DPAD;
        sWih[i] = (col < Dn) ? Wih[row * Dn + col] : 0.0f;
    }
    for (int i = tid; i < Gn; i += NTH) sbias[i] = bih[i] + bhh[i];
    if (tid < Hn)   sb1[tid] = b1[tid];
    if (tid < DPAD) sb2[tid] = (tid < Dn) ? b2[tid] : 0.0f;
    for (int i = tid; i < RPB * Hn; i += NTH) { sh[i] = 0.0f; sc[i] = 0.0f; }
    __syncthreads();

    for (int t = 0; t < Tn; ++t) {
        // ---- Prefetch x_t for Phase C (warps 0..3); hidden under A/B ----
        float xv0 = 0.f, xv1 = 0.f, xv2 = 0.f;
        if (wid < 4) {
            const float* xrow = X + ((size_t)(b0i + wid) * Tn + t) * Dn;
            xv0 = xrow[lane];
            xv1 = xrow[lane + 32];
            if (lane < Dn - 64) xv2 = xrow[lane + 64];
        }

        // ---- h,c K-slices into registers (reused by Phases A and D) ----
        float4 hA[4], cA[4];
        #pragma unroll
        for (int r = 0; r < RPB; ++r) {
            hA[r] = *(const float4*)(sh + r * Hn + 4 * lane);
            cA[r] = *(const float4*)(sc + r * Hn + 4 * lane);
        }

        // ===== Phase A: a1 = tanh(W1 @ [h;c] + b1); 4 j per warp =====
        {
            #pragma unroll
            for (int oi = 0; oi < 4; ++oi) {
                const int j = wid * 4 + oi;
                const float4* w = (const float4*)(W1 + (size_t)j * (2 * Hn));
                float4 wh = __ldg(w + lane);        // dense 512B across warp
                float4 wc = __ldg(w + 32 + lane);
                float p[4];
                #pragma unroll
                for (int r = 0; r < RPB; ++r)
                    p[r] = dot4(wc, cA[r], dot4(wh, hA[r], 0.0f));
                float d; int o;
                reduce4_32(p, lane, d, o);
                if (lane < 4) sa1[o * A1PAD + j] = tanh_f(d + sb1[j]);
            }
        }
        __syncthreads();

        // ===== Phase B: e = W2 @ a1 + b2; 3 j per warp (warps 0..26) =====
        if (wid < 27) {
            float4 aA[4];
            #pragma unroll
            for (int r = 0; r < RPB; ++r)
                aA[r] = *(const float4*)(sa1 + r * A1PAD + 4 * lane);
            #pragma unroll
            for (int oi = 0; oi < 3; ++oi) {
                const int j = wid * 3 + oi;
                float4 w = __ldg((const float4*)(W2 + (size_t)j * Hn) + lane);
                float p[4];
                #pragma unroll
                for (int r = 0; r < RPB; ++r)
                    p[r] = dot4(w, aA[r], 0.0f);
                float d; int o;
                reduce4_32(p, lane, d, o);
                if (lane < 4) se[o * DPAD + j] = d + sb2[j];
            }
        }
        __syncthreads();

        // ===== Phase C: softmax over D (no max-sub: |e| <= ~11.4 provably,
        // exp(e) <= 9e4, sum <= 7.5e6 -> fp32-safe); warps 0..3 =====
        if (wid < 4) {
            const int cr = wid;
            const int cl = lane;
            float* er = se + cr * DPAD;
            float e0 = __expf(er[cl]);
            float e1 = __expf(er[cl + 32]);
            float e2 = (cl < Dn - 64) ? __expf(er[cl + 64]) : 0.0f;
            float ssum = e0 + e1 + e2;
            #pragma unroll
            for (int s = 16; s; s >>= 1) ssum += __shfl_xor_sync(0xffffffffu, ssum, s);
            const float inv = __fdividef(1.0f, ssum);

            float* xwr  = sxw + cr * DPAD;
            float* arow = outA + ((size_t)(b0i + cr) * Tn + t) * Dn;

            float a0 = e0 * inv;
            stcs(arow + cl, a0);          xwr[cl]      = a0 * xv0;
            float a1v = e1 * inv;
            stcs(arow + cl + 32, a1v);    xwr[cl + 32] = a1v * xv1;
            if (cl < Dn - 64) {
                float a2 = e2 * inv;
                stcs(arow + cl + 64, a2); xwr[cl + 64] = a2 * xv2;
            }
            if (cl < DPAD - Dn) xwr[Dn + cl] = 0.0f;   // zero pad cols 81..83
        }
        __syncthreads();

        // ===== Phase D: gates = W_ih @ xw + W_hh @ h + bias; 16 j/warp =====
        {
            const bool act21 = (lane < 21);      // 4*lane < 84
            float4 zz = make_float4(0.f, 0.f, 0.f, 0.f);
            float4 xwA[4];
            #pragma unroll
            for (int r = 0; r < RPB; ++r)
                xwA[r] = act21 ? *(const float4*)(sxw + r * DPAD + 4 * lane) : zz;

            #pragma unroll 4
            for (int oi = 0; oi < 16; ++oi) {
                const int j = wid * 16 + oi;
                float4 wh4 = __ldg((const float4*)(Whh + (size_t)j * Hn) + lane);
                // predicated: inactive lanes contribute zero, fetch nothing
                float4 wi4 = act21 ? ((const float4*)(sWih + j * DPAD))[lane] : zz;
                float p[4];
                #pragma unroll
                for (int r = 0; r < RPB; ++r)
                    p[r] = dot4(wh4, hA[r], dot4(wi4, xwA[r], 0.0f));
                float d; int o;
                reduce4_32(p, lane, d, o);
                if (lane < 4) sgate[o * GPAD + j] = d + sbias[j];
            }
        }
        __syncthreads();

        // ===== Phase E: LSTM cell update, write h out (512 threads) =====
        if (tid < RPB * Hn) {
            const int rr  = tid >> 7;
            const int col = tid & (Hn - 1);
            float gi = sgate[rr * GPAD + col];
            float gf = sgate[rr * GPAD + Hn + col];
            float gg = sgate[rr * GPAD + 2 * Hn + col];
            float go = sgate[rr * GPAD + 3 * Hn + col];
            float si = sigmoid_f(gi);
            float sf = sigmoid_f(gf);
            float so = sigmoid_f(go);
            float cn = sf * sc[rr * Hn + col] + si * tanh_f(gg);
            float hn = so * tanh_f(cn);
            sc[rr * Hn + col] = cn;
            sh[rr * Hn + col] = hn;
            stcs(outH + ((size_t)(b0i + rr) * Tn + t) * Hn + col, hn);
        }
        __syncthreads();
    }
}

extern "C" void kernel_launch(void* const* d_in, const int* in_sizes, int n_in,
                              void* d_out, int out_size)
{
    const float* X    = (const float*)d_in[0];
    const float* W1   = (const float*)d_in[1];
    const float* b1   = (const float*)d_in[2];
    const float* W2   = (const float*)d_in[3];
    const float* b2   = (const float*)d_in[4];
    const float* Wih  = (const float*)d_in[5];
    const float* Whh  = (const float*)d_in[6];
    const float* bih  = (const float*)d_in[7];
    const float* bhh  = (const float*)d_in[8];

    float* outH = (float*)d_out;                          // [B, T, H]
    float* outA = outH + (size_t)Bsz * Tn * Hn;           // [B, T, D]

    const size_t smem_bytes = (size_t)SMEM_FLOATS * sizeof(float);
    cudaFuncSetAttribute(encoder_kernel,
                         cudaFuncAttributeMaxDynamicSharedMemorySize,
                         (int)smem_bytes);

    encoder_kernel<<<NBLK, NTH, smem_bytes>>>(
        X, W1, b1, W2, b2, Wih, Whh, bih, bhh, outH, outA);
}